// round 12
// baseline (speedup 1.0000x reference)
#include <cuda_runtime.h>
#include <cstdint>

#define NN 512000       // nodes = 512 * 1000
#define NE 8192000      // edges per branch
#define NB 512          // batch
#define NS 1000         // stations
#define NH 64           // ff hidden
#define NA 1024         // actions
#define EPSF 1e-5f

#define TB 256
#define STATS_BLKS 1024
#define EDGE_BLKS8 4000         // 4000 * 256 * 8 = NE exactly

// ---------------- scratch ----------------------------------------------------
__device__ float    g_stats[3][16];        // per branch: sum[8], sumsq[8]
__device__ unsigned g_deg[3][NN];          // edge-count per dst (no self loop)
__device__ float4   g_z1[3][NN];           // xw * dinv
__device__ float4   g_acc1[3][NN];         // conv1 accumulator (init = self loop)
__device__ float    g_z2[3][NN];
__device__ float    g_acc2[3][NN];

// ---------------- kernels ----------------------------------------------------

__global__ void zeroK() {
    int i = blockIdx.x * blockDim.x + threadIdx.x;
    if (i < 3 * NN) ((unsigned*)g_deg)[i] = 0u;
    if (i < 48)     ((float*)g_stats)[i] = 0.f;
}

// blocks [0,STATS_BLKS) do feature stats, rest do deg histogram (8 edges/thr).
__global__ void statsdegK(const float* __restrict__ x0, const float* __restrict__ x1,
                          const float* __restrict__ x2,
                          const int* __restrict__ e0, const int* __restrict__ e1,
                          const int* __restrict__ e2) {
    int br = blockIdx.y;
    if (blockIdx.x < STATS_BLKS) {
        const float* x = br == 0 ? x0 : (br == 1 ? x1 : x2);
        float s[8], q[8];
#pragma unroll
        for (int i = 0; i < 8; i++) { s[i] = 0.f; q[i] = 0.f; }
        int stride = STATS_BLKS * TB;
        for (int n = blockIdx.x * TB + threadIdx.x; n < NN; n += stride) {
            const float4* p = (const float4*)(x + (size_t)n * 8);
            float4 a = __ldg(p), b = __ldg(p + 1);
            float v[8] = {a.x, a.y, a.z, a.w, b.x, b.y, b.z, b.w};
#pragma unroll
            for (int i = 0; i < 8; i++) { s[i] += v[i]; q[i] += v[i] * v[i]; }
        }
#pragma unroll
        for (int i = 0; i < 8; i++) {
#pragma unroll
            for (int o = 16; o; o >>= 1) {
                s[i] += __shfl_down_sync(0xffffffffu, s[i], o);
                q[i] += __shfl_down_sync(0xffffffffu, q[i], o);
            }
        }
        __shared__ float sh[16];
        if (threadIdx.x < 16) sh[threadIdx.x] = 0.f;
        __syncthreads();
        if ((threadIdx.x & 31) == 0) {
#pragma unroll
            for (int i = 0; i < 8; i++) {
                atomicAdd(&sh[i], s[i]);
                atomicAdd(&sh[8 + i], q[i]);
            }
        }
        __syncthreads();
        if (threadIdx.x < 16) atomicAdd(&g_stats[br][threadIdx.x], sh[threadIdx.x]);
    } else {
        const int* ei = br == 0 ? e0 : (br == 1 ? e1 : e2);
        int base = (blockIdx.x - STATS_BLKS) * 2048 + threadIdx.x * 8;
        int4 a = __ldg((const int4*)(ei + NE + base));
        int4 b = __ldg((const int4*)(ei + NE + base + 4));
        atomicAdd(&g_deg[br][a.x], 1u);
        atomicAdd(&g_deg[br][a.y], 1u);
        atomicAdd(&g_deg[br][a.z], 1u);
        atomicAdd(&g_deg[br][a.w], 1u);
        atomicAdd(&g_deg[br][b.x], 1u);
        atomicAdd(&g_deg[br][b.y], 1u);
        atomicAdd(&g_deg[br][b.z], 1u);
        atomicAdd(&g_deg[br][b.w], 1u);
    }
}

// z1 = (norm(x)@W1)*dinv, GraphNorm affine folded in (thread 0 per block).
__global__ void z1K(const float* __restrict__ x0, const float* __restrict__ x1,
                    const float* __restrict__ x2,
                    const float* __restrict__ nw, const float* __restrict__ nbp,
                    const float* __restrict__ nms, const float* __restrict__ W1) {
    int br = blockIdx.y;
    const float* x = br == 0 ? x0 : (br == 1 ? x1 : x2);
    __shared__ float sA[32];
    __shared__ float sD[4];
    if (threadIdx.x == 0) {
        const float inv = 1.0f / (float)NN;
        float a[8], d[8];
#pragma unroll
        for (int i = 0; i < 8; i++) {
            float mean = g_stats[br][i] * inv;
            float m2   = g_stats[br][8 + i] * inv;
            float c    = mean * nms[i];
            float var  = m2 - 2.f * c * mean + c * c;
            float ai   = nw[i] * rsqrtf(var + EPSF);
            a[i] = ai;
            d[i] = nbp[i] - c * ai;
        }
#pragma unroll
        for (int j = 0; j < 4; j++) {
            float dv = 0.f;
#pragma unroll
            for (int i = 0; i < 8; i++) {
                sA[i * 4 + j] = a[i] * W1[i * 4 + j];
                dv += d[i] * W1[i * 4 + j];
            }
            sD[j] = dv;
        }
    }
    __syncthreads();
    int n = blockIdx.x * TB + threadIdx.x;
    if (n >= NN) return;
    const float4* p = (const float4*)(x + (size_t)n * 8);
    float4 a = __ldg(p), b = __ldg(p + 1);
    float v[8] = {a.x, a.y, a.z, a.w, b.x, b.y, b.z, b.w};
    float dinv = rsqrtf((float)(g_deg[br][n] + 1u));
    float o[4];
#pragma unroll
    for (int j = 0; j < 4; j++) {
        float acc = sD[j];
#pragma unroll
        for (int i = 0; i < 8; i++) acc += v[i] * sA[i * 4 + j];
        o[j] = acc * dinv;
    }
    float4 z = make_float4(o[0], o[1], o[2], o[3]);
    g_z1[br][n]  = z;
    g_acc1[br][n] = z;
}

// conv1 edge scatter, 8 edges/thread: acc1[dst] += z1[src]
__global__ void scat1K(const int* __restrict__ e0, const int* __restrict__ e1,
                       const int* __restrict__ e2) {
    int br = blockIdx.y;
    const int* ei = br == 0 ? e0 : (br == 1 ? e1 : e2);
    int base = blockIdx.x * 2048 + threadIdx.x * 8;
    int4 sa = __ldg((const int4*)(ei + base));
    int4 sb = __ldg((const int4*)(ei + base + 4));
    int4 da = __ldg((const int4*)(ei + NE + base));
    int4 db = __ldg((const int4*)(ei + NE + base + 4));
    float4 z0 = __ldg(&g_z1[br][sa.x]);
    float4 z1 = __ldg(&g_z1[br][sa.y]);
    float4 z2 = __ldg(&g_z1[br][sa.z]);
    float4 z3 = __ldg(&g_z1[br][sa.w]);
    float4 z4 = __ldg(&g_z1[br][sb.x]);
    float4 z5 = __ldg(&g_z1[br][sb.y]);
    float4 z6 = __ldg(&g_z1[br][sb.z]);
    float4 z7 = __ldg(&g_z1[br][sb.w]);
    atomicAdd(&g_acc1[br][da.x], z0);
    atomicAdd(&g_acc1[br][da.y], z1);
    atomicAdd(&g_acc1[br][da.z], z2);
    atomicAdd(&g_acc1[br][da.w], z3);
    atomicAdd(&g_acc1[br][db.x], z4);
    atomicAdd(&g_acc1[br][db.y], z5);
    atomicAdd(&g_acc1[br][db.z], z6);
    atomicAdd(&g_acc1[br][db.w], z7);
}

// h1 = relu(dinv*acc1 + b1); z2 = (h1 . w2) * dinv; acc2 init = z2
__global__ void h1z2K(const float* __restrict__ b1, const float* __restrict__ w2) {
    int br = blockIdx.y;
    int n = blockIdx.x * TB + threadIdx.x;
    if (n >= NN) return;
    float dinv = rsqrtf((float)(g_deg[br][n] + 1u));
    float4 acc = g_acc1[br][n];
    float h0 = fmaxf(fmaf(dinv, acc.x, b1[0]), 0.f);
    float h1 = fmaxf(fmaf(dinv, acc.y, b1[1]), 0.f);
    float h2 = fmaxf(fmaf(dinv, acc.z, b1[2]), 0.f);
    float h3 = fmaxf(fmaf(dinv, acc.w, b1[3]), 0.f);
    float z2 = (h0 * w2[0] + h1 * w2[1] + h2 * w2[2] + h3 * w2[3]) * dinv;
    g_z2[br][n]  = z2;
    g_acc2[br][n] = z2;
}

// conv2 edge scatter, 8 edges/thread: acc2[dst] += z2[src]
__global__ void scat2K(const int* __restrict__ e0, const int* __restrict__ e1,
                       const int* __restrict__ e2) {
    int br = blockIdx.y;
    const int* ei = br == 0 ? e0 : (br == 1 ? e1 : e2);
    int base = blockIdx.x * 2048 + threadIdx.x * 8;
    int4 sa = __ldg((const int4*)(ei + base));
    int4 sb = __ldg((const int4*)(ei + base + 4));
    int4 da = __ldg((const int4*)(ei + NE + base));
    int4 db = __ldg((const int4*)(ei + NE + base + 4));
    float v0 = __ldg(&g_z2[br][sa.x]);
    float v1 = __ldg(&g_z2[br][sa.y]);
    float v2 = __ldg(&g_z2[br][sa.z]);
    float v3 = __ldg(&g_z2[br][sa.w]);
    float v4 = __ldg(&g_z2[br][sb.x]);
    float v5 = __ldg(&g_z2[br][sb.y]);
    float v6 = __ldg(&g_z2[br][sb.z]);
    float v7 = __ldg(&g_z2[br][sb.w]);
    atomicAdd(&g_acc2[br][da.x], v0);
    atomicAdd(&g_acc2[br][da.y], v1);
    atomicAdd(&g_acc2[br][da.z], v2);
    atomicAdd(&g_acc2[br][da.w], v3);
    atomicAdd(&g_acc2[br][db.x], v4);
    atomicAdd(&g_acc2[br][db.y], v5);
    atomicAdd(&g_acc2[br][db.z], v6);
    atomicAdd(&g_acc2[br][db.w], v7);
}

// fused FF head: conv2 epilogue + concat + ff1 + relu + ff2 + mask.
// One block handles 2 batch rows end-to-end (hidden stays in smem).
__global__ void ffK(const float* __restrict__ b2, const float* __restrict__ w1f,
                    const float* __restrict__ b1f, const float* __restrict__ w2f,
                    const float* __restrict__ b2f, const float* __restrict__ mask,
                    float* __restrict__ out) {
    __shared__ float row[2 * 3 * NS];      // 24 KB
    __shared__ float part[8][NH];          // [r*4+g][j]
    __shared__ float hid[2 * NH];
    int b0 = blockIdx.x * 2;
    float b2v = __ldg(b2);
    int tid = threadIdx.x;
    for (int e = tid; e < 2 * 3 * NS; e += TB) {
        int r  = e / (3 * NS);
        int kk = e - r * (3 * NS);
        int br = kk / NS;
        int s  = kk - br * NS;
        int n  = (b0 + r) * NS + s;
        float dinv = rsqrtf((float)(g_deg[br][n] + 1u));
        row[e] = fmaxf(fmaf(dinv, g_acc2[br][n], b2v), 0.f);
    }
    __syncthreads();
    int g = tid >> 6;                       // k-quarter 0..3
    int j = tid & 63;                       // hidden col
    float a0 = 0.f, a1 = 0.f;
    int k0 = g * 750, k1 = k0 + 750;
    for (int k = k0; k < k1; ++k) {
        float wv = __ldg(w1f + (size_t)k * NH + j);
        a0 = fmaf(row[k], wv, a0);
        a1 = fmaf(row[3 * NS + k], wv, a1);
    }
    part[g][j]     = a0;
    part[4 + g][j] = a1;
    __syncthreads();
    if (tid < 2 * NH) {
        int r = tid >> 6;
        int c = tid & 63;
        float v = part[r * 4 + 0][c] + part[r * 4 + 1][c] +
                  part[r * 4 + 2][c] + part[r * 4 + 3][c] + b1f[c];
        hid[tid] = fmaxf(v, 0.f);
    }
    __syncthreads();
    for (int o = tid; o < NA; o += TB) {
        float s0 = b2f[o], s1 = s0;
#pragma unroll 8
        for (int k = 0; k < NH; k++) {
            float wv = __ldg(w2f + (size_t)k * NA + o);
            s0 = fmaf(hid[k], wv, s0);
            s1 = fmaf(hid[NH + k], wv, s1);
        }
        size_t i0 = (size_t)b0 * NA + o;
        size_t i1 = i0 + NA;
        out[i0] = s0 * mask[i0];
        out[i1] = s1 * mask[i1];
    }
}

// ---------------- launch ------------------------------------------------------

extern "C" void kernel_launch(void* const* d_in, const int* in_sizes, int n_in,
                              void* d_out, int out_size) {
    const float* x0 = (const float*)d_in[0];
    const float* x1 = (const float*)d_in[1];
    const float* x2 = (const float*)d_in[2];
    const int* e0 = (const int*)d_in[3];
    const int* e1 = (const int*)d_in[4];
    const int* e2 = (const int*)d_in[5];
    const float* mask = (const float*)d_in[6];
    const float* nw  = (const float*)d_in[7];
    const float* nb  = (const float*)d_in[8];
    const float* nms = (const float*)d_in[9];
    const float* W1  = (const float*)d_in[10];
    const float* b1  = (const float*)d_in[11];
    const float* W2  = (const float*)d_in[12];
    const float* b2  = (const float*)d_in[13];
    const float* wf1 = (const float*)d_in[14];
    const float* bf1 = (const float*)d_in[15];
    const float* wf2 = (const float*)d_in[16];
    const float* bf2 = (const float*)d_in[17];
    float* out = (float*)d_out;

    dim3 gridSD(STATS_BLKS + EDGE_BLKS8, 3);
    dim3 gridE(EDGE_BLKS8, 3);
    dim3 gridN((NN + TB - 1) / TB, 3);

    zeroK<<<(3 * NN + TB - 1) / TB, TB>>>();
    statsdegK<<<gridSD, TB>>>(x0, x1, x2, e0, e1, e2);
    z1K<<<gridN, TB>>>(x0, x1, x2, nw, nb, nms, W1);
    scat1K<<<gridE, TB>>>(e0, e1, e2);
    h1z2K<<<gridN, TB>>>(b1, W2);
    scat2K<<<gridE, TB>>>(e0, e1, e2);
    ffK<<<NB / 2, TB>>>(b2, wf1, bf1, wf2, bf2, mask, out);
}

// round 13
// speedup vs baseline: 1.0177x; 1.0177x over previous
#include <cuda_runtime.h>
#include <cstdint>

#define NN 512000       // nodes = 512 * 1000
#define NE 8192000      // edges per branch
#define NB 512          // batch
#define NS 1000         // stations
#define NH 64           // ff hidden
#define NA 1024         // actions
#define EPSF 1e-5f

#define TB 256
#define STATS_BLKS 1024
#define EDGE_BLKS 8000          // 8000 * 256 * 4 = NE exactly

// ---------------- scratch ----------------------------------------------------
__device__ float    g_stats[3][16];        // per branch: sum[8], sumsq[8]
__device__ unsigned g_deg[3][NN];          // edge-count per dst (no self loop)
__device__ float4   g_z1[3][NN];           // xw * dinv
__device__ float4   g_acc1[3][NN];         // conv1 accumulator (init = self loop)
__device__ float    g_z2[3][NN];
__device__ float    g_acc2[3][NN];

// ---------------- kernels ----------------------------------------------------

__global__ void zeroK() {
    int i = blockIdx.x * blockDim.x + threadIdx.x;
    if (i < 3 * NN) ((unsigned*)g_deg)[i] = 0u;
    if (i < 48)     ((float*)g_stats)[i] = 0.f;
}

// blocks [0,STATS_BLKS) do feature stats, rest do deg histogram (4 edges/thr).
__global__ void statsdegK(const float* __restrict__ x0, const float* __restrict__ x1,
                          const float* __restrict__ x2,
                          const int* __restrict__ e0, const int* __restrict__ e1,
                          const int* __restrict__ e2) {
    int br = blockIdx.y;
    if (blockIdx.x < STATS_BLKS) {
        const float* x = br == 0 ? x0 : (br == 1 ? x1 : x2);
        float s[8], q[8];
#pragma unroll
        for (int i = 0; i < 8; i++) { s[i] = 0.f; q[i] = 0.f; }
        int stride = STATS_BLKS * TB;
        for (int n = blockIdx.x * TB + threadIdx.x; n < NN; n += stride) {
            const float4* p = (const float4*)(x + (size_t)n * 8);
            float4 a = __ldg(p), b = __ldg(p + 1);
            float v[8] = {a.x, a.y, a.z, a.w, b.x, b.y, b.z, b.w};
#pragma unroll
            for (int i = 0; i < 8; i++) { s[i] += v[i]; q[i] += v[i] * v[i]; }
        }
#pragma unroll
        for (int i = 0; i < 8; i++) {
#pragma unroll
            for (int o = 16; o; o >>= 1) {
                s[i] += __shfl_down_sync(0xffffffffu, s[i], o);
                q[i] += __shfl_down_sync(0xffffffffu, q[i], o);
            }
        }
        __shared__ float sh[16];
        if (threadIdx.x < 16) sh[threadIdx.x] = 0.f;
        __syncthreads();
        if ((threadIdx.x & 31) == 0) {
#pragma unroll
            for (int i = 0; i < 8; i++) {
                atomicAdd(&sh[i], s[i]);
                atomicAdd(&sh[8 + i], q[i]);
            }
        }
        __syncthreads();
        if (threadIdx.x < 16) atomicAdd(&g_stats[br][threadIdx.x], sh[threadIdx.x]);
    } else {
        const int* ei = br == 0 ? e0 : (br == 1 ? e1 : e2);
        int base = (blockIdx.x - STATS_BLKS) * 1024 + threadIdx.x * 4;
        int4 d4 = __ldg((const int4*)(ei + NE + base));
        atomicAdd(&g_deg[br][d4.x], 1u);
        atomicAdd(&g_deg[br][d4.y], 1u);
        atomicAdd(&g_deg[br][d4.z], 1u);
        atomicAdd(&g_deg[br][d4.w], 1u);
    }
}

// z1 = (norm(x)@W1)*dinv, GraphNorm affine folded in (thread 0 per block).
__global__ void z1K(const float* __restrict__ x0, const float* __restrict__ x1,
                    const float* __restrict__ x2,
                    const float* __restrict__ nw, const float* __restrict__ nbp,
                    const float* __restrict__ nms, const float* __restrict__ W1) {
    int br = blockIdx.y;
    const float* x = br == 0 ? x0 : (br == 1 ? x1 : x2);
    __shared__ float sA[32];
    __shared__ float sD[4];
    if (threadIdx.x == 0) {
        const float inv = 1.0f / (float)NN;
        float a[8], d[8];
#pragma unroll
        for (int i = 0; i < 8; i++) {
            float mean = g_stats[br][i] * inv;
            float m2   = g_stats[br][8 + i] * inv;
            float c    = mean * nms[i];
            float var  = m2 - 2.f * c * mean + c * c;
            float ai   = nw[i] * rsqrtf(var + EPSF);
            a[i] = ai;
            d[i] = nbp[i] - c * ai;
        }
#pragma unroll
        for (int j = 0; j < 4; j++) {
            float dv = 0.f;
#pragma unroll
            for (int i = 0; i < 8; i++) {
                sA[i * 4 + j] = a[i] * W1[i * 4 + j];
                dv += d[i] * W1[i * 4 + j];
            }
            sD[j] = dv;
        }
    }
    __syncthreads();
    int n = blockIdx.x * TB + threadIdx.x;
    if (n >= NN) return;
    const float4* p = (const float4*)(x + (size_t)n * 8);
    float4 a = __ldg(p), b = __ldg(p + 1);
    float v[8] = {a.x, a.y, a.z, a.w, b.x, b.y, b.z, b.w};
    float dinv = rsqrtf((float)(g_deg[br][n] + 1u));
    float o[4];
#pragma unroll
    for (int j = 0; j < 4; j++) {
        float acc = sD[j];
#pragma unroll
        for (int i = 0; i < 8; i++) acc += v[i] * sA[i * 4 + j];
        o[j] = acc * dinv;
    }
    float4 z = make_float4(o[0], o[1], o[2], o[3]);
    g_z1[br][n]  = z;
    g_acc1[br][n] = z;
}

// conv1 edge scatter, 4 edges/thread: acc1[dst] += z1[src]
__global__ void scat1K(const int* __restrict__ e0, const int* __restrict__ e1,
                       const int* __restrict__ e2) {
    int br = blockIdx.y;
    const int* ei = br == 0 ? e0 : (br == 1 ? e1 : e2);
    int base = blockIdx.x * 1024 + threadIdx.x * 4;
    int4 s4 = __ldg((const int4*)(ei + base));
    int4 d4 = __ldg((const int4*)(ei + NE + base));
    float4 z0 = __ldg(&g_z1[br][s4.x]);
    float4 z1 = __ldg(&g_z1[br][s4.y]);
    float4 z2 = __ldg(&g_z1[br][s4.z]);
    float4 z3 = __ldg(&g_z1[br][s4.w]);
    atomicAdd(&g_acc1[br][d4.x], z0);
    atomicAdd(&g_acc1[br][d4.y], z1);
    atomicAdd(&g_acc1[br][d4.z], z2);
    atomicAdd(&g_acc1[br][d4.w], z3);
}

// h1 = relu(dinv*acc1 + b1); z2 = (h1 . w2) * dinv; acc2 init = z2
__global__ void h1z2K(const float* __restrict__ b1, const float* __restrict__ w2) {
    int br = blockIdx.y;
    int n = blockIdx.x * TB + threadIdx.x;
    if (n >= NN) return;
    float dinv = rsqrtf((float)(g_deg[br][n] + 1u));
    float4 acc = g_acc1[br][n];
    float h0 = fmaxf(fmaf(dinv, acc.x, b1[0]), 0.f);
    float h1 = fmaxf(fmaf(dinv, acc.y, b1[1]), 0.f);
    float h2 = fmaxf(fmaf(dinv, acc.z, b1[2]), 0.f);
    float h3 = fmaxf(fmaf(dinv, acc.w, b1[3]), 0.f);
    float z2 = (h0 * w2[0] + h1 * w2[1] + h2 * w2[2] + h3 * w2[3]) * dinv;
    g_z2[br][n]  = z2;
    g_acc2[br][n] = z2;
}

// conv2 edge scatter, 4 edges/thread: acc2[dst] += z2[src]
__global__ void scat2K(const int* __restrict__ e0, const int* __restrict__ e1,
                       const int* __restrict__ e2) {
    int br = blockIdx.y;
    const int* ei = br == 0 ? e0 : (br == 1 ? e1 : e2);
    int base = blockIdx.x * 1024 + threadIdx.x * 4;
    int4 s4 = __ldg((const int4*)(ei + base));
    int4 d4 = __ldg((const int4*)(ei + NE + base));
    float v0 = __ldg(&g_z2[br][s4.x]);
    float v1 = __ldg(&g_z2[br][s4.y]);
    float v2 = __ldg(&g_z2[br][s4.z]);
    float v3 = __ldg(&g_z2[br][s4.w]);
    atomicAdd(&g_acc2[br][d4.x], v0);
    atomicAdd(&g_acc2[br][d4.y], v1);
    atomicAdd(&g_acc2[br][d4.z], v2);
    atomicAdd(&g_acc2[br][d4.w], v3);
}

// fused FF head: conv2 epilogue + concat + ff1 + relu + ff2 + mask.
// One block handles 2 batch rows end-to-end (hidden stays in smem).
__global__ void ffK(const float* __restrict__ b2, const float* __restrict__ w1f,
                    const float* __restrict__ b1f, const float* __restrict__ w2f,
                    const float* __restrict__ b2f, const float* __restrict__ mask,
                    float* __restrict__ out) {
    __shared__ float row[2 * 3 * NS];      // 24 KB
    __shared__ float part[8][NH];          // [r*4+g][j]
    __shared__ float hid[2 * NH];
    int b0 = blockIdx.x * 2;
    float b2v = __ldg(b2);
    int tid = threadIdx.x;
    for (int e = tid; e < 2 * 3 * NS; e += TB) {
        int r  = e / (3 * NS);
        int kk = e - r * (3 * NS);
        int br = kk / NS;
        int s  = kk - br * NS;
        int n  = (b0 + r) * NS + s;
        float dinv = rsqrtf((float)(g_deg[br][n] + 1u));
        row[e] = fmaxf(fmaf(dinv, g_acc2[br][n], b2v), 0.f);
    }
    __syncthreads();
    int g = tid >> 6;                       // k-quarter 0..3
    int j = tid & 63;                       // hidden col
    float a0 = 0.f, a1 = 0.f;
    int k0 = g * 750, k1 = k0 + 750;
    for (int k = k0; k < k1; ++k) {
        float wv = __ldg(w1f + (size_t)k * NH + j);
        a0 = fmaf(row[k], wv, a0);
        a1 = fmaf(row[3 * NS + k], wv, a1);
    }
    part[g][j]     = a0;
    part[4 + g][j] = a1;
    __syncthreads();
    if (tid < 2 * NH) {
        int r = tid >> 6;
        int c = tid & 63;
        float v = part[r * 4 + 0][c] + part[r * 4 + 1][c] +
                  part[r * 4 + 2][c] + part[r * 4 + 3][c] + b1f[c];
        hid[tid] = fmaxf(v, 0.f);
    }
    __syncthreads();
    for (int o = tid; o < NA; o += TB) {
        float s0 = b2f[o], s1 = s0;
#pragma unroll 8
        for (int k = 0; k < NH; k++) {
            float wv = __ldg(w2f + (size_t)k * NA + o);
            s0 = fmaf(hid[k], wv, s0);
            s1 = fmaf(hid[NH + k], wv, s1);
        }
        size_t i0 = (size_t)b0 * NA + o;
        size_t i1 = i0 + NA;
        out[i0] = s0 * mask[i0];
        out[i1] = s1 * mask[i1];
    }
}

// ---------------- launch ------------------------------------------------------

extern "C" void kernel_launch(void* const* d_in, const int* in_sizes, int n_in,
                              void* d_out, int out_size) {
    const float* x0 = (const float*)d_in[0];
    const float* x1 = (const float*)d_in[1];
    const float* x2 = (const float*)d_in[2];
    const int* e0 = (const int*)d_in[3];
    const int* e1 = (const int*)d_in[4];
    const int* e2 = (const int*)d_in[5];
    const float* mask = (const float*)d_in[6];
    const float* nw  = (const float*)d_in[7];
    const float* nb  = (const float*)d_in[8];
    const float* nms = (const float*)d_in[9];
    const float* W1  = (const float*)d_in[10];
    const float* b1  = (const float*)d_in[11];
    const float* W2  = (const float*)d_in[12];
    const float* b2  = (const float*)d_in[13];
    const float* wf1 = (const float*)d_in[14];
    const float* bf1 = (const float*)d_in[15];
    const float* wf2 = (const float*)d_in[16];
    const float* bf2 = (const float*)d_in[17];
    float* out = (float*)d_out;

    dim3 gridSD(STATS_BLKS + EDGE_BLKS, 3);
    dim3 gridE(EDGE_BLKS, 3);
    dim3 gridN((NN + TB - 1) / TB, 3);

    zeroK<<<(3 * NN + TB - 1) / TB, TB>>>();
    statsdegK<<<gridSD, TB>>>(x0, x1, x2, e0, e1, e2);
    z1K<<<gridN, TB>>>(x0, x1, x2, nw, nb, nms, W1);
    scat1K<<<gridE, TB>>>(e0, e1, e2);
    h1z2K<<<gridN, TB>>>(b1, W2);
    scat2K<<<gridE, TB>>>(e0, e1, e2);
    ffK<<<NB / 2, TB>>>(b2, wf1, bf1, wf2, bf2, mask, out);
}

// round 15
// speedup vs baseline: 1.1772x; 1.1568x over previous
#include <cuda_runtime.h>
#include <cstdint>

#define NN 512000       // nodes = 512 * 1000
#define NE 8192000      // edges per branch
#define NB 512          // batch
#define NS 1000         // stations
#define NH 64           // ff hidden
#define NA 1024         // actions
#define EPSF 1e-5f

#define TB 256
#define STATS_BLKS 1024
#define EDGE_BLKS 8000          // 8000 * 256 * 4 = NE exactly

// ---------------- scratch ----------------------------------------------------
__device__ float    g_stats[3][16];        // per branch: sum[8], sumsq[8]
__device__ unsigned g_deg[3][NN];          // edge-count per dst (no self loop)
__device__ float4   g_z1[3][NN];           // xw * dinv
__device__ float4   g_acc1[3][NN];         // conv1 accumulator (init = self loop)
__device__ float    g_z2[3][NN];
__device__ float    g_acc2[3][NN];
__device__ float    g_hidden[NB * NH];     // ff1 output

// ---------------- kernels ----------------------------------------------------

__global__ void zeroK() {
    int i = blockIdx.x * blockDim.x + threadIdx.x;
    if (i < 3 * NN) ((unsigned*)g_deg)[i] = 0u;
    if (i < 48)     ((float*)g_stats)[i] = 0.f;
}

// blocks [0,STATS_BLKS) do feature stats, rest do deg histogram. y = branch.
__global__ void statsdegK(const float* __restrict__ x0, const float* __restrict__ x1,
                          const float* __restrict__ x2,
                          const int* __restrict__ e0, const int* __restrict__ e1,
                          const int* __restrict__ e2) {
    int br = blockIdx.y;
    if (blockIdx.x < STATS_BLKS) {
        const float* x = br == 0 ? x0 : (br == 1 ? x1 : x2);
        float s[8], q[8];
#pragma unroll
        for (int i = 0; i < 8; i++) { s[i] = 0.f; q[i] = 0.f; }
        int stride = STATS_BLKS * TB;
        for (int n = blockIdx.x * TB + threadIdx.x; n < NN; n += stride) {
            const float4* p = (const float4*)(x + (size_t)n * 8);
            float4 a = __ldg(p), b = __ldg(p + 1);
            float v[8] = {a.x, a.y, a.z, a.w, b.x, b.y, b.z, b.w};
#pragma unroll
            for (int i = 0; i < 8; i++) { s[i] += v[i]; q[i] += v[i] * v[i]; }
        }
#pragma unroll
        for (int i = 0; i < 8; i++) {
#pragma unroll
            for (int o = 16; o; o >>= 1) {
                s[i] += __shfl_down_sync(0xffffffffu, s[i], o);
                q[i] += __shfl_down_sync(0xffffffffu, q[i], o);
            }
        }
        __shared__ float sh[16];
        if (threadIdx.x < 16) sh[threadIdx.x] = 0.f;
        __syncthreads();
        if ((threadIdx.x & 31) == 0) {
#pragma unroll
            for (int i = 0; i < 8; i++) {
                atomicAdd(&sh[i], s[i]);
                atomicAdd(&sh[8 + i], q[i]);
            }
        }
        __syncthreads();
        if (threadIdx.x < 16) atomicAdd(&g_stats[br][threadIdx.x], sh[threadIdx.x]);
    } else {
        const int* ei = br == 0 ? e0 : (br == 1 ? e1 : e2);
        int base = (blockIdx.x - STATS_BLKS) * 1024 + threadIdx.x * 4;
        int4 d4 = __ldg((const int4*)(ei + NE + base));
        atomicAdd(&g_deg[br][d4.x], 1u);
        atomicAdd(&g_deg[br][d4.y], 1u);
        atomicAdd(&g_deg[br][d4.z], 1u);
        atomicAdd(&g_deg[br][d4.w], 1u);
    }
}

// z1 = (norm(x)@W1)*dinv, GraphNorm affine folded in (thread 0 per block).
__global__ void z1K(const float* __restrict__ x0, const float* __restrict__ x1,
                    const float* __restrict__ x2,
                    const float* __restrict__ nw, const float* __restrict__ nbp,
                    const float* __restrict__ nms, const float* __restrict__ W1) {
    int br = blockIdx.y;
    const float* x = br == 0 ? x0 : (br == 1 ? x1 : x2);
    __shared__ float sA[32];
    __shared__ float sD[4];
    if (threadIdx.x == 0) {
        const float inv = 1.0f / (float)NN;
        float a[8], d[8];
#pragma unroll
        for (int i = 0; i < 8; i++) {
            float mean = g_stats[br][i] * inv;
            float m2   = g_stats[br][8 + i] * inv;
            float c    = mean * nms[i];
            float var  = m2 - 2.f * c * mean + c * c;
            float ai   = nw[i] * rsqrtf(var + EPSF);
            a[i] = ai;
            d[i] = nbp[i] - c * ai;
        }
#pragma unroll
        for (int j = 0; j < 4; j++) {
            float dv = 0.f;
#pragma unroll
            for (int i = 0; i < 8; i++) {
                sA[i * 4 + j] = a[i] * W1[i * 4 + j];
                dv += d[i] * W1[i * 4 + j];
            }
            sD[j] = dv;
        }
    }
    __syncthreads();
    int n = blockIdx.x * TB + threadIdx.x;
    if (n >= NN) return;
    const float4* p = (const float4*)(x + (size_t)n * 8);
    float4 a = __ldg(p), b = __ldg(p + 1);
    float v[8] = {a.x, a.y, a.z, a.w, b.x, b.y, b.z, b.w};
    float dinv = rsqrtf((float)(g_deg[br][n] + 1u));
    float o[4];
#pragma unroll
    for (int j = 0; j < 4; j++) {
        float acc = sD[j];
#pragma unroll
        for (int i = 0; i < 8; i++) acc += v[i] * sA[i * 4 + j];
        o[j] = acc * dinv;
    }
    float4 z = make_float4(o[0], o[1], o[2], o[3]);
    g_z1[br][n]  = z;
    g_acc1[br][n] = z;
}

// conv1 edge scatter, 4 edges/thread: acc1[dst] += z1[src]
__global__ void scat1K(const int* __restrict__ e0, const int* __restrict__ e1,
                       const int* __restrict__ e2) {
    int br = blockIdx.y;
    const int* ei = br == 0 ? e0 : (br == 1 ? e1 : e2);
    int base = blockIdx.x * 1024 + threadIdx.x * 4;
    int4 s4 = __ldg((const int4*)(ei + base));
    int4 d4 = __ldg((const int4*)(ei + NE + base));
    float4 z0 = __ldg(&g_z1[br][s4.x]);
    float4 z1 = __ldg(&g_z1[br][s4.y]);
    float4 z2 = __ldg(&g_z1[br][s4.z]);
    float4 z3 = __ldg(&g_z1[br][s4.w]);
    atomicAdd(&g_acc1[br][d4.x], z0);
    atomicAdd(&g_acc1[br][d4.y], z1);
    atomicAdd(&g_acc1[br][d4.z], z2);
    atomicAdd(&g_acc1[br][d4.w], z3);
}

// h1 = relu(dinv*acc1 + b1); z2 = (h1 . w2) * dinv; acc2 init = z2
__global__ void h1z2K(const float* __restrict__ b1, const float* __restrict__ w2) {
    int br = blockIdx.y;
    int n = blockIdx.x * TB + threadIdx.x;
    if (n >= NN) return;
    float dinv = rsqrtf((float)(g_deg[br][n] + 1u));
    float4 acc = g_acc1[br][n];
    float h0 = fmaxf(fmaf(dinv, acc.x, b1[0]), 0.f);
    float h1 = fmaxf(fmaf(dinv, acc.y, b1[1]), 0.f);
    float h2 = fmaxf(fmaf(dinv, acc.z, b1[2]), 0.f);
    float h3 = fmaxf(fmaf(dinv, acc.w, b1[3]), 0.f);
    float z2 = (h0 * w2[0] + h1 * w2[1] + h2 * w2[2] + h3 * w2[3]) * dinv;
    g_z2[br][n]  = z2;
    g_acc2[br][n] = z2;
}

// conv2 edge scatter, 4 edges/thread: acc2[dst] += z2[src]
__global__ void scat2K(const int* __restrict__ e0, const int* __restrict__ e1,
                       const int* __restrict__ e2) {
    int br = blockIdx.y;
    const int* ei = br == 0 ? e0 : (br == 1 ? e1 : e2);
    int base = blockIdx.x * 1024 + threadIdx.x * 4;
    int4 s4 = __ldg((const int4*)(ei + base));
    int4 d4 = __ldg((const int4*)(ei + NE + base));
    float v0 = __ldg(&g_z2[br][s4.x]);
    float v1 = __ldg(&g_z2[br][s4.y]);
    float v2 = __ldg(&g_z2[br][s4.z]);
    float v3 = __ldg(&g_z2[br][s4.w]);
    atomicAdd(&g_acc2[br][d4.x], v0);
    atomicAdd(&g_acc2[br][d4.y], v1);
    atomicAdd(&g_acc2[br][d4.z], v2);
    atomicAdd(&g_acc2[br][d4.w], v3);
}

// ff1, 2 batch rows per block (grid NB/2): concat rows in smem (conv2 epilogue
// fused), shared w-stream amortized over both rows.
__global__ void ff1K(const float* __restrict__ b2, const float* __restrict__ w,
                     const float* __restrict__ bias) {
    __shared__ float row[2 * 3 * NS];      // 24000 B
    __shared__ float part[8][NH];          // [r*4+g][j]
    int b0 = blockIdx.x * 2;
    float b2v = __ldg(b2);
    int tid = threadIdx.x;
    for (int e = tid; e < 2 * 3 * NS; e += TB) {
        int r  = e / (3 * NS);
        int kk = e - r * (3 * NS);
        int br = kk / NS;
        int s  = kk - br * NS;
        int n  = (b0 + r) * NS + s;
        float dinv = rsqrtf((float)(g_deg[br][n] + 1u));
        row[e] = fmaxf(fmaf(dinv, g_acc2[br][n], b2v), 0.f);
    }
    __syncthreads();
    int g = tid >> 6;                       // k-quarter 0..3
    int j = tid & 63;                       // hidden col
    float a0 = 0.f, a1 = 0.f;
    int k0 = g * 750, k1 = k0 + 750;
    for (int k = k0; k < k1; ++k) {
        float wv = __ldg(w + (size_t)k * NH + j);
        a0 = fmaf(row[k], wv, a0);
        a1 = fmaf(row[3 * NS + k], wv, a1);
    }
    part[g][j]     = a0;
    part[4 + g][j] = a1;
    __syncthreads();
    if (tid < 2 * NH) {
        int r = tid >> 6;
        int c = tid & 63;
        float v = part[r * 4 + 0][c] + part[r * 4 + 1][c] +
                  part[r * 4 + 2][c] + part[r * 4 + 3][c] + bias[c];
        g_hidden[(b0 + r) * NH + c] = fmaxf(v, 0.f);
    }
}

// ff2, 2 batch rows per block: out = hidden @ w2f + b2f, * mask
__global__ void ff2K(const float* __restrict__ w, const float* __restrict__ bias,
                     const float* __restrict__ mask, float* __restrict__ out) {
    __shared__ float h[2 * NH];
    int b0 = blockIdx.x * 2;
    int tid = threadIdx.x;
    if (tid < 2 * NH) h[tid] = g_hidden[b0 * NH + tid];
    __syncthreads();
    for (int o = tid; o < NA; o += TB) {
        float a0 = bias[o], a1 = a0;
#pragma unroll 8
        for (int k = 0; k < NH; k++) {
            float wv = __ldg(w + (size_t)k * NA + o);
            a0 = fmaf(h[k], wv, a0);
            a1 = fmaf(h[NH + k], wv, a1);
        }
        size_t i0 = (size_t)b0 * NA + o;
        size_t i1 = i0 + NA;
        out[i0] = a0 * mask[i0];
        out[i1] = a1 * mask[i1];
    }
}

// ---------------- launch ------------------------------------------------------

extern "C" void kernel_launch(void* const* d_in, const int* in_sizes, int n_in,
                              void* d_out, int out_size) {
    const float* x0 = (const float*)d_in[0];
    const float* x1 = (const float*)d_in[1];
    const float* x2 = (const float*)d_in[2];
    const int* e0 = (const int*)d_in[3];
    const int* e1 = (const int*)d_in[4];
    const int* e2 = (const int*)d_in[5];
    const float* mask = (const float*)d_in[6];
    const float* nw  = (const float*)d_in[7];
    const float* nb  = (const float*)d_in[8];
    const float* nms = (const float*)d_in[9];
    const float* W1  = (const float*)d_in[10];
    const float* b1  = (const float*)d_in[11];
    const float* W2  = (const float*)d_in[12];
    const float* b2  = (const float*)d_in[13];
    const float* wf1 = (const float*)d_in[14];
    const float* bf1 = (const float*)d_in[15];
    const float* wf2 = (const float*)d_in[16];
    const float* bf2 = (const float*)d_in[17];
    float* out = (float*)d_out;

    dim3 gridSD(STATS_BLKS + EDGE_BLKS, 3);
    dim3 gridE(EDGE_BLKS, 3);
    dim3 gridN((NN + TB - 1) / TB, 3);

    zeroK<<<(3 * NN + TB - 1) / TB, TB>>>();
    statsdegK<<<gridSD, TB>>>(x0, x1, x2, e0, e1, e2);
    z1K<<<gridN, TB>>>(x0, x1, x2, nw, nb, nms, W1);
    scat1K<<<gridE, TB>>>(e0, e1, e2);
    h1z2K<<<gridN, TB>>>(b1, W2);
    scat2K<<<gridE, TB>>>(e0, e1, e2);
    ff1K<<<NB / 2, TB>>>(b2, wf1, bf1);
    ff2K<<<NB / 2, TB>>>(wf2, bf2, mask, out);
}

// round 17
// speedup vs baseline: 1.1773x; 1.0001x over previous
#include <cuda_runtime.h>
#include <cstdint>

#define NN 512000       // nodes = 512 * 1000
#define NE 8192000      // edges per branch
#define NB 512          // batch
#define NS 1000         // stations
#define NH 64           // ff hidden
#define NA 1024         // actions
#define EPSF 1e-5f

#define TB 256
#define STATS_BLKS 1024
#define EDGE_BLKS 8000          // 8000 * 256 * 4 = NE exactly

// ---------------- scratch ----------------------------------------------------
__device__ float    g_stats[3][16];        // per branch: sum[8], sumsq[8]
__device__ unsigned g_deg[3][NN];          // edge-count per dst (no self loop)
__device__ float4   g_z1[3][NN];           // xw * dinv
__device__ float4   g_acc1[3][NN];         // conv1 accumulator (init = self loop)
__device__ float    g_z2[3][NN];
__device__ float    g_acc2[3][NN];
__device__ float    g_hidden[NB * NH];     // ff1 output

// ---------------- kernels ----------------------------------------------------

__global__ void zeroK() {
    int i = blockIdx.x * blockDim.x + threadIdx.x;
    if (i < 3 * NN) ((unsigned*)g_deg)[i] = 0u;
    if (i < 48)     ((float*)g_stats)[i] = 0.f;
}

// blocks [0,STATS_BLKS) do feature stats, rest do deg histogram. y = branch.
__global__ void statsdegK(const float* __restrict__ x0, const float* __restrict__ x1,
                          const float* __restrict__ x2,
                          const int* __restrict__ e0, const int* __restrict__ e1,
                          const int* __restrict__ e2) {
    int br = blockIdx.y;
    if (blockIdx.x < STATS_BLKS) {
        const float* x = br == 0 ? x0 : (br == 1 ? x1 : x2);
        float s[8], q[8];
#pragma unroll
        for (int i = 0; i < 8; i++) { s[i] = 0.f; q[i] = 0.f; }
        int stride = STATS_BLKS * TB;
        for (int n = blockIdx.x * TB + threadIdx.x; n < NN; n += stride) {
            const float4* p = (const float4*)(x + (size_t)n * 8);
            float4 a = __ldg(p), b = __ldg(p + 1);
            float v[8] = {a.x, a.y, a.z, a.w, b.x, b.y, b.z, b.w};
#pragma unroll
            for (int i = 0; i < 8; i++) { s[i] += v[i]; q[i] += v[i] * v[i]; }
        }
#pragma unroll
        for (int i = 0; i < 8; i++) {
#pragma unroll
            for (int o = 16; o; o >>= 1) {
                s[i] += __shfl_down_sync(0xffffffffu, s[i], o);
                q[i] += __shfl_down_sync(0xffffffffu, q[i], o);
            }
        }
        __shared__ float sh[16];
        if (threadIdx.x < 16) sh[threadIdx.x] = 0.f;
        __syncthreads();
        if ((threadIdx.x & 31) == 0) {
#pragma unroll
            for (int i = 0; i < 8; i++) {
                atomicAdd(&sh[i], s[i]);
                atomicAdd(&sh[8 + i], q[i]);
            }
        }
        __syncthreads();
        if (threadIdx.x < 16) atomicAdd(&g_stats[br][threadIdx.x], sh[threadIdx.x]);
    } else {
        const int* ei = br == 0 ? e0 : (br == 1 ? e1 : e2);
        int base = (blockIdx.x - STATS_BLKS) * 1024 + threadIdx.x * 4;
        int4 d4 = __ldg((const int4*)(ei + NE + base));
        atomicAdd(&g_deg[br][d4.x], 1u);
        atomicAdd(&g_deg[br][d4.y], 1u);
        atomicAdd(&g_deg[br][d4.z], 1u);
        atomicAdd(&g_deg[br][d4.w], 1u);
    }
}

// z1 = (norm(x)@W1)*dinv, GraphNorm affine folded in (thread 0 per block).
__global__ void z1K(const float* __restrict__ x0, const float* __restrict__ x1,
                    const float* __restrict__ x2,
                    const float* __restrict__ nw, const float* __restrict__ nbp,
                    const float* __restrict__ nms, const float* __restrict__ W1) {
    int br = blockIdx.y;
    const float* x = br == 0 ? x0 : (br == 1 ? x1 : x2);
    __shared__ float sA[32];
    __shared__ float sD[4];
    if (threadIdx.x == 0) {
        const float inv = 1.0f / (float)NN;
        float a[8], d[8];
#pragma unroll
        for (int i = 0; i < 8; i++) {
            float mean = g_stats[br][i] * inv;
            float m2   = g_stats[br][8 + i] * inv;
            float c    = mean * nms[i];
            float var  = m2 - 2.f * c * mean + c * c;
            float ai   = nw[i] * rsqrtf(var + EPSF);
            a[i] = ai;
            d[i] = nbp[i] - c * ai;
        }
#pragma unroll
        for (int j = 0; j < 4; j++) {
            float dv = 0.f;
#pragma unroll
            for (int i = 0; i < 8; i++) {
                sA[i * 4 + j] = a[i] * W1[i * 4 + j];
                dv += d[i] * W1[i * 4 + j];
            }
            sD[j] = dv;
        }
    }
    __syncthreads();
    int n = blockIdx.x * TB + threadIdx.x;
    if (n >= NN) return;
    const float4* p = (const float4*)(x + (size_t)n * 8);
    float4 a = __ldg(p), b = __ldg(p + 1);
    float v[8] = {a.x, a.y, a.z, a.w, b.x, b.y, b.z, b.w};
    float dinv = rsqrtf((float)(g_deg[br][n] + 1u));
    float o[4];
#pragma unroll
    for (int j = 0; j < 4; j++) {
        float acc = sD[j];
#pragma unroll
        for (int i = 0; i < 8; i++) acc += v[i] * sA[i * 4 + j];
        o[j] = acc * dinv;
    }
    float4 z = make_float4(o[0], o[1], o[2], o[3]);
    g_z1[br][n]  = z;
    g_acc1[br][n] = z;
}

// conv1 edge scatter, 4 edges/thread: acc1[dst] += z1[src]
__global__ void scat1K(const int* __restrict__ e0, const int* __restrict__ e1,
                       const int* __restrict__ e2) {
    int br = blockIdx.y;
    const int* ei = br == 0 ? e0 : (br == 1 ? e1 : e2);
    int base = blockIdx.x * 1024 + threadIdx.x * 4;
    int4 s4 = __ldg((const int4*)(ei + base));
    int4 d4 = __ldg((const int4*)(ei + NE + base));
    float4 z0 = __ldg(&g_z1[br][s4.x]);
    float4 z1 = __ldg(&g_z1[br][s4.y]);
    float4 z2 = __ldg(&g_z1[br][s4.z]);
    float4 z3 = __ldg(&g_z1[br][s4.w]);
    atomicAdd(&g_acc1[br][d4.x], z0);
    atomicAdd(&g_acc1[br][d4.y], z1);
    atomicAdd(&g_acc1[br][d4.z], z2);
    atomicAdd(&g_acc1[br][d4.w], z3);
}

// h1 = relu(dinv*acc1 + b1); z2 = (h1 . w2) * dinv; acc2 init = z2
__global__ void h1z2K(const float* __restrict__ b1, const float* __restrict__ w2) {
    int br = blockIdx.y;
    int n = blockIdx.x * TB + threadIdx.x;
    if (n >= NN) return;
    float dinv = rsqrtf((float)(g_deg[br][n] + 1u));
    float4 acc = g_acc1[br][n];
    float h0 = fmaxf(fmaf(dinv, acc.x, b1[0]), 0.f);
    float h1 = fmaxf(fmaf(dinv, acc.y, b1[1]), 0.f);
    float h2 = fmaxf(fmaf(dinv, acc.z, b1[2]), 0.f);
    float h3 = fmaxf(fmaf(dinv, acc.w, b1[3]), 0.f);
    float z2 = (h0 * w2[0] + h1 * w2[1] + h2 * w2[2] + h3 * w2[3]) * dinv;
    g_z2[br][n]  = z2;
    g_acc2[br][n] = z2;
}

// conv2 edge scatter, 4 edges/thread: acc2[dst] += z2[src]
__global__ void scat2K(const int* __restrict__ e0, const int* __restrict__ e1,
                       const int* __restrict__ e2) {
    int br = blockIdx.y;
    const int* ei = br == 0 ? e0 : (br == 1 ? e1 : e2);
    int base = blockIdx.x * 1024 + threadIdx.x * 4;
    int4 s4 = __ldg((const int4*)(ei + base));
    int4 d4 = __ldg((const int4*)(ei + NE + base));
    float v0 = __ldg(&g_z2[br][s4.x]);
    float v1 = __ldg(&g_z2[br][s4.y]);
    float v2 = __ldg(&g_z2[br][s4.z]);
    float v3 = __ldg(&g_z2[br][s4.w]);
    atomicAdd(&g_acc2[br][d4.x], v0);
    atomicAdd(&g_acc2[br][d4.y], v1);
    atomicAdd(&g_acc2[br][d4.z], v2);
    atomicAdd(&g_acc2[br][d4.w], v3);
}

// ff1, 2 batch rows per block (grid NB/2): concat rows in smem (conv2 epilogue
// fused), shared w-stream amortized over both rows.
__global__ void ff1K(const float* __restrict__ b2, const float* __restrict__ w,
                     const float* __restrict__ bias) {
    __shared__ float row[2 * 3 * NS];      // 24000 B
    __shared__ float part[8][NH];          // [r*4+g][j]
    int b0 = blockIdx.x * 2;
    float b2v = __ldg(b2);
    int tid = threadIdx.x;
    for (int e = tid; e < 2 * 3 * NS; e += TB) {
        int r  = e / (3 * NS);
        int kk = e - r * (3 * NS);
        int br = kk / NS;
        int s  = kk - br * NS;
        int n  = (b0 + r) * NS + s;
        float dinv = rsqrtf((float)(g_deg[br][n] + 1u));
        row[e] = fmaxf(fmaf(dinv, g_acc2[br][n], b2v), 0.f);
    }
    __syncthreads();
    int g = tid >> 6;                       // k-quarter 0..3
    int j = tid & 63;                       // hidden col
    float a0 = 0.f, a1 = 0.f;
    int k0 = g * 750, k1 = k0 + 750;
    for (int k = k0; k < k1; ++k) {
        float wv = __ldg(w + (size_t)k * NH + j);
        a0 = fmaf(row[k], wv, a0);
        a1 = fmaf(row[3 * NS + k], wv, a1);
    }
    part[g][j]     = a0;
    part[4 + g][j] = a1;
    __syncthreads();
    if (tid < 2 * NH) {
        int r = tid >> 6;
        int c = tid & 63;
        float v = part[r * 4 + 0][c] + part[r * 4 + 1][c] +
                  part[r * 4 + 2][c] + part[r * 4 + 3][c] + bias[c];
        g_hidden[(b0 + r) * NH + c] = fmaxf(v, 0.f);
    }
}

// ff2, 2 batch rows per block: out = hidden @ w2f + b2f, * mask
__global__ void ff2K(const float* __restrict__ w, const float* __restrict__ bias,
                     const float* __restrict__ mask, float* __restrict__ out) {
    __shared__ float h[2 * NH];
    int b0 = blockIdx.x * 2;
    int tid = threadIdx.x;
    if (tid < 2 * NH) h[tid] = g_hidden[b0 * NH + tid];
    __syncthreads();
    for (int o = tid; o < NA; o += TB) {
        float a0 = bias[o], a1 = a0;
#pragma unroll 8
        for (int k = 0; k < NH; k++) {
            float wv = __ldg(w + (size_t)k * NA + o);
            a0 = fmaf(h[k], wv, a0);
            a1 = fmaf(h[NH + k], wv, a1);
        }
        size_t i0 = (size_t)b0 * NA + o;
        size_t i1 = i0 + NA;
        out[i0] = a0 * mask[i0];
        out[i1] = a1 * mask[i1];
    }
}

// ---------------- launch ------------------------------------------------------

extern "C" void kernel_launch(void* const* d_in, const int* in_sizes, int n_in,
                              void* d_out, int out_size) {
    const float* x0 = (const float*)d_in[0];
    const float* x1 = (const float*)d_in[1];
    const float* x2 = (const float*)d_in[2];
    const int* e0 = (const int*)d_in[3];
    const int* e1 = (const int*)d_in[4];
    const int* e2 = (const int*)d_in[5];
    const float* mask = (const float*)d_in[6];
    const float* nw  = (const float*)d_in[7];
    const float* nb  = (const float*)d_in[8];
    const float* nms = (const float*)d_in[9];
    const float* W1  = (const float*)d_in[10];
    const float* b1  = (const float*)d_in[11];
    const float* W2  = (const float*)d_in[12];
    const float* b2  = (const float*)d_in[13];
    const float* wf1 = (const float*)d_in[14];
    const float* bf1 = (const float*)d_in[15];
    const float* wf2 = (const float*)d_in[16];
    const float* bf2 = (const float*)d_in[17];
    float* out = (float*)d_out;

    dim3 gridSD(STATS_BLKS + EDGE_BLKS, 3);
    dim3 gridE(EDGE_BLKS, 3);
    dim3 gridN((NN + TB - 1) / TB, 3);

    zeroK<<<(3 * NN + TB - 1) / TB, TB>>>();
    statsdegK<<<gridSD, TB>>>(x0, x1, x2, e0, e1, e2);
    z1K<<<gridN, TB>>>(x0, x1, x2, nw, nb, nms, W1);
    scat1K<<<gridE, TB>>>(e0, e1, e2);
    h1z2K<<<gridN, TB>>>(b1, W2);
    scat2K<<<gridE, TB>>>(e0, e1, e2);
    ff1K<<<NB / 2, TB>>>(b2, wf1, bf1);
    ff2K<<<NB / 2, TB>>>(wf2, bf2, mask, out);
}